// round 9
// baseline (speedup 1.0000x reference)
#include <cuda_runtime.h>

// LSTM: B=1024, T=2048, H=32, I=1.
// TWO warps per batch element, split by GATE PAIR (not k):
//   warp0: (i,f) preacts over full k; warp1: (g,o) preacts over full k.
// Producer/consumer named barriers (bar.arrive / bar.sync), one wait per warp
// per step. Lane j owns hidden unit j. Gates packed in f32x2; h broadcast via
// duplicated smem pairs. sigmoid(a)=0.5*tanh(a/2)+0.5 (pre-scaled), MUFU.TANH.

#define B_ 1024
#define T_ 2048
#define H_ 32

typedef unsigned long long u64;

static __device__ __forceinline__ u64 pk2(float lo, float hi) {
    u64 r;
    asm("mov.b64 %0, {%1, %2};" : "=l"(r) : "f"(lo), "f"(hi));
    return r;
}
static __device__ __forceinline__ void upk2(u64 v, float& lo, float& hi) {
    asm("mov.b64 {%0, %1}, %2;" : "=f"(lo), "=f"(hi) : "l"(v));
}
static __device__ __forceinline__ u64 fma2(u64 a, u64 b, u64 c) {
    u64 d;
    asm("fma.rn.f32x2 %0, %1, %2, %3;" : "=l"(d) : "l"(a), "l"(b), "l"(c));
    return d;
}
static __device__ __forceinline__ u64 add2(u64 a, u64 b) {
    u64 d;
    asm("add.rn.f32x2 %0, %1, %2;" : "=l"(d) : "l"(a), "l"(b));
    return d;
}
static __device__ __forceinline__ float tanhf_(float x) {
    float r; asm("tanh.approx.f32 %0, %1;" : "=f"(r) : "f"(x)); return r;
}
static __device__ __forceinline__ void lds2(u64& p0, u64& p1, unsigned addr) {
    asm volatile("ld.shared.v2.b64 {%0, %1}, [%2];"
                 : "=l"(p0), "=l"(p1) : "r"(addr));
}
static __device__ __forceinline__ u64 lds64(unsigned addr) {
    u64 v;
    asm volatile("ld.shared.b64 %0, [%1];" : "=l"(v) : "r"(addr));
    return v;
}
static __device__ __forceinline__ void sts64(unsigned addr, u64 v) {
    asm volatile("st.shared.b64 [%0], %1;" :: "r"(addr), "l"(v));
}
static __device__ __forceinline__ void bar_arrive(int id) {
    asm volatile("bar.arrive %0, 64;" :: "r"(id) : "memory");
}
static __device__ __forceinline__ void bar_sync(int id) {
    asm volatile("bar.sync %0, 64;" :: "r"(id) : "memory");
}

__global__ void __launch_bounds__(64)
lstm_kernel(const float* __restrict__ x,
            const float* __restrict__ W_ih,
            const float* __restrict__ W_hh,
            const float* __restrict__ b_ih,
            const float* __restrict__ b_hh,
            const float* __restrict__ W_out,
            const float* __restrict__ b_out,
            float* __restrict__ out) {
    const int j = threadIdx.x & 31;   // hidden unit
    const int w = threadIdx.x >> 5;   // 0: (i,f) producer; 1: (g,o)+state owner
    const int b = blockIdx.x;

    __shared__ u64 hbuf[2][H_];       // duplicated (h,h) pairs, double-buffered
    __shared__ u64 ifbuf[H_];         // (i_, f_) hand-off w0 -> w1
    __shared__ float pbuf[32][33];    // per-step output partials (w1 only)
    volatile float (*pv)[33] = (volatile float (*)[33])pbuf;

    const float sI = 0.5f, sF = 0.5f, sG = 1.0f, sO = 0.5f;

    // Uniform gate-phase registers; data differs per warp.
    // w0: (sI*W_i, sF*W_f); w1: (sG*W_g, sO*W_o)
    u64 wreg[H_];
    const int r0 = (w == 0) ? 0 : 2;   // first gate row block
    const int r1 = (w == 0) ? 1 : 3;   // second gate row block
    const float s0 = (w == 0) ? sI : sG;
    const float s1 = (w == 0) ? sF : sO;
#pragma unroll
    for (int k = 0; k < H_; k++) {
        wreg[k] = pk2(s0 * W_hh[(r0 * H_ + j) * H_ + k],
                      s1 * W_hh[(r1 * H_ + j) * H_ + k]);
    }
    const u64 wih = pk2(s0 * W_ih[r0 * H_ + j], s1 * W_ih[r1 * H_ + j]);
    const u64 bsc = pk2(s0 * (b_ih[r0 * H_ + j] + b_hh[r0 * H_ + j]),
                        s1 * (b_ih[r1 * H_ + j] + b_hh[r1 * H_ + j]));
    const float wout = W_out[j];
    const float bout = b_out[0];
    const u64 z2 = 0ull;

    const unsigned hb0 = (unsigned)__cvta_generic_to_shared(&hbuf[0][0]);
    const unsigned hb1 = hb0 + (unsigned)(H_ * sizeof(u64));
    const unsigned ifb = (unsigned)__cvta_generic_to_shared(&ifbuf[0]);

    float c = 0.0f;
    if (w == 1) sts64(hb0 + j * 8, z2);   // h_{-1} = 0 (w1 owns state)
    __syncthreads();

    const float* xb = x + (size_t)b * T_;
    float* ob = out + (size_t)b * T_;
    float xc = xb[0];

    for (int t0 = 0; t0 < T_; t0 += 32) {
#pragma unroll 2
        for (int tt = 0; tt < 32; ++tt) {
            const int t = t0 + tt;
            const int tn = (t + 1 < T_) ? (t + 1) : (T_ - 1);
            const float xn = xb[tn];

            const unsigned rd = (t & 1) ? hb1 : hb0;         // h(t)
            const unsigned wr = ((t & 1) ? hb0 : hb1) + j * 8; // h(t+1)

            // ---- Gate phase (identical code both warps; 8 chains of 4) ----
            const u64 xd = pk2(xc, xc);
            u64 p0, p1, p2, p3, p4, p5, p6, p7;
            lds2(p0, p1, rd);
            lds2(p2, p3, rd + 16);
            lds2(p4, p5, rd + 32);
            lds2(p6, p7, rd + 48);
            u64 q0, q1, q2, q3, q4, q5, q6, q7;
            lds2(q0, q1, rd + 64);
            lds2(q2, q3, rd + 80);
            lds2(q4, q5, rd + 96);
            lds2(q6, q7, rd + 112);

            u64 a0 = fma2(xd, wih, bsc);
            u64 a1 = z2, a2 = z2, a3 = z2, a4 = z2, a5 = z2, a6 = z2, a7 = z2;
            a0 = fma2(p0, wreg[0], a0);
            a1 = fma2(p1, wreg[1], a1);
            a2 = fma2(p2, wreg[2], a2);
            a3 = fma2(p3, wreg[3], a3);
            a4 = fma2(p4, wreg[4], a4);
            a5 = fma2(p5, wreg[5], a5);
            a6 = fma2(p6, wreg[6], a6);
            a7 = fma2(p7, wreg[7], a7);
            a0 = fma2(q0, wreg[8],  a0);
            a1 = fma2(q1, wreg[9],  a1);
            a2 = fma2(q2, wreg[10], a2);
            a3 = fma2(q3, wreg[11], a3);
            a4 = fma2(q4, wreg[12], a4);
            a5 = fma2(q5, wreg[13], a5);
            a6 = fma2(q6, wreg[14], a6);
            a7 = fma2(q7, wreg[15], a7);
            lds2(p0, p1, rd + 128);
            lds2(p2, p3, rd + 144);
            lds2(p4, p5, rd + 160);
            lds2(p6, p7, rd + 176);
            lds2(q0, q1, rd + 192);
            lds2(q2, q3, rd + 208);
            lds2(q4, q5, rd + 224);
            lds2(q6, q7, rd + 240);
            a0 = fma2(p0, wreg[16], a0);
            a1 = fma2(p1, wreg[17], a1);
            a2 = fma2(p2, wreg[18], a2);
            a3 = fma2(p3, wreg[19], a3);
            a4 = fma2(p4, wreg[20], a4);
            a5 = fma2(p5, wreg[21], a5);
            a6 = fma2(p6, wreg[22], a6);
            a7 = fma2(p7, wreg[23], a7);
            a0 = fma2(q0, wreg[24], a0);
            a1 = fma2(q1, wreg[25], a1);
            a2 = fma2(q2, wreg[26], a2);
            a3 = fma2(q3, wreg[27], a3);
            a4 = fma2(q4, wreg[28], a4);
            a5 = fma2(q5, wreg[29], a5);
            a6 = fma2(q6, wreg[30], a6);
            a7 = fma2(q7, wreg[31], a7);
            const u64 acc = add2(add2(add2(a0, a1), add2(a2, a3)),
                                 add2(add2(a4, a5), add2(a6, a7)));

            float v0, v1;
            upk2(acc, v0, v1);
            const float tv0 = tanhf_(v0);
            const float tv1 = tanhf_(v1);

            if (w == 0) {
                // (i,f): post activations, hand off, then wait for h(t+1).
                const float i_ = fmaf(tv0, 0.5f, 0.5f);
                const float f_ = fmaf(tv1, 0.5f, 0.5f);
                sts64(ifb + j * 8, pk2(i_, f_));
                bar_arrive(1);
                bar_sync(2);        // h(t+1) visible
            } else {
                // (g,o): own the cell state; consume (i,f), produce h.
                const float g_ = tv0;
                const float o_ = fmaf(tv1, 0.5f, 0.5f);
                bar_sync(1);        // (i,f) visible
                float i_, f_;
                upk2(lds64(ifb + j * 8), i_, f_);
                c = fmaf(f_, c, i_ * g_);
                const float h = o_ * tanhf_(c);
                sts64(wr, pk2(h, h));
                bar_arrive(2);      // release h to w0
                pv[tt][j] = h * wout;
            }
            xc = xn;
        }
        // Output reduction (w1): lane j sums the 32 partials of timestep t0+j.
        if (w == 1) {
            float s0_ = 0.0f, s1_ = 0.0f, s2_ = 0.0f, s3_ = 0.0f;
#pragma unroll
            for (int k = 0; k < 32; k += 4) {
                s0_ += pv[j][k];
                s1_ += pv[j][k + 1];
                s2_ += pv[j][k + 2];
                s3_ += pv[j][k + 3];
            }
            ob[t0 + j] = (s0_ + s1_) + (s2_ + s3_) + bout;
        }
    }
}

extern "C" void kernel_launch(void* const* d_in, const int* in_sizes, int n_in,
                              void* d_out, int out_size) {
    const float* x     = (const float*)d_in[0];
    const float* W_ih  = (const float*)d_in[1];
    const float* W_hh  = (const float*)d_in[2];
    const float* b_ih  = (const float*)d_in[3];
    const float* b_hh  = (const float*)d_in[4];
    const float* W_out = (const float*)d_in[5];
    const float* b_out = (const float*)d_in[6];
    float* out = (float*)d_out;

    lstm_kernel<<<B_, 64>>>(x, W_ih, W_hh, b_ih, b_hh, W_out, b_out, out);
}

// round 10
// speedup vs baseline: 1.2895x; 1.2895x over previous
#include <cuda_runtime.h>

// LSTM: B=1024, T=2048, H=32, I=1.
// One warp, TWO sequences, HALF-STEP SKEW:
//   ... gatesB(t) || tailA(t),  gatesA(t+1) || tailB(t) ...
// Gate phase = fused k-loop with 1-group LDS lookahead, 8 accumulator chains
// (R8 engine). Tail = 4 parallel MUFU.TANH + c/h update + h broadcast store.
// Lane j owns hidden unit j; gates packed (i,f),(g,o) in f32x2; h broadcast
// via duplicated smem pairs (double-buffered; converged warp -> no syncs).
// sigmoid(a)=0.5*tanh(a/2)+0.5 with pre-scaled weights.

#define B_ 1024
#define T_ 2048
#define H_ 32

typedef unsigned long long u64;

static __device__ __forceinline__ u64 pk2(float lo, float hi) {
    u64 r;
    asm("mov.b64 %0, {%1, %2};" : "=l"(r) : "f"(lo), "f"(hi));
    return r;
}
static __device__ __forceinline__ void upk2(u64 v, float& lo, float& hi) {
    asm("mov.b64 {%0, %1}, %2;" : "=f"(lo), "=f"(hi) : "l"(v));
}
static __device__ __forceinline__ u64 fma2(u64 a, u64 b, u64 c) {
    u64 d;
    asm("fma.rn.f32x2 %0, %1, %2, %3;" : "=l"(d) : "l"(a), "l"(b), "l"(c));
    return d;
}
static __device__ __forceinline__ u64 add2(u64 a, u64 b) {
    u64 d;
    asm("add.rn.f32x2 %0, %1, %2;" : "=l"(d) : "l"(a), "l"(b));
    return d;
}
static __device__ __forceinline__ float tanhf_(float x) {
    float r; asm("tanh.approx.f32 %0, %1;" : "=f"(r) : "f"(x)); return r;
}
static __device__ __forceinline__ void lds2(u64& p0, u64& p1, unsigned addr) {
    asm volatile("ld.shared.v2.b64 {%0, %1}, [%2];"
                 : "=l"(p0), "=l"(p1) : "r"(addr));
}
static __device__ __forceinline__ void sts64(unsigned addr, u64 v) {
    asm volatile("st.shared.b64 [%0], %1;" :: "r"(addr), "l"(v));
}

__global__ void __launch_bounds__(32)
lstm_kernel(const float* __restrict__ x,
            const float* __restrict__ W_ih,
            const float* __restrict__ W_hh,
            const float* __restrict__ b_ih,
            const float* __restrict__ b_hh,
            const float* __restrict__ W_out,
            const float* __restrict__ b_out,
            float* __restrict__ out) {
    const int j  = threadIdx.x;
    const int bA = blockIdx.x * 2;
    const int bB = bA + 1;

    __shared__ u64 hA[2][H_];
    __shared__ u64 hB[2][H_];
    __shared__ float pbufA[32][33];
    __shared__ float pbufB[32][33];
    volatile float (*pvA)[33] = (volatile float (*)[33])pbufA;
    volatile float (*pvB)[33] = (volatile float (*)[33])pbufB;

    const float sI = 0.5f, sF = 0.5f, sG = 1.0f, sO = 0.5f;

    u64 wif[H_], wgo[H_];
#pragma unroll
    for (int k = 0; k < H_; k++) {
        wif[k] = pk2(sI * W_hh[(0 * H_ + j) * H_ + k],
                     sF * W_hh[(1 * H_ + j) * H_ + k]);
        wgo[k] = pk2(sG * W_hh[(2 * H_ + j) * H_ + k],
                     sO * W_hh[(3 * H_ + j) * H_ + k]);
    }
    const u64 wih_if = pk2(sI * W_ih[0 * H_ + j], sF * W_ih[1 * H_ + j]);
    const u64 wih_go = pk2(sG * W_ih[2 * H_ + j], sO * W_ih[3 * H_ + j]);
    const u64 bs_if  = pk2(sI * (b_ih[0 * H_ + j] + b_hh[0 * H_ + j]),
                           sF * (b_ih[1 * H_ + j] + b_hh[1 * H_ + j]));
    const u64 bs_go  = pk2(sG * (b_ih[2 * H_ + j] + b_hh[2 * H_ + j]),
                           sO * (b_ih[3 * H_ + j] + b_hh[3 * H_ + j]));
    const float wout = W_out[j];
    const float bout = b_out[0];
    const u64 z2 = 0ull;

    const unsigned hA0 = (unsigned)__cvta_generic_to_shared(&hA[0][0]);
    const unsigned hA1 = hA0 + (unsigned)(H_ * sizeof(u64));
    const unsigned hB0 = (unsigned)__cvta_generic_to_shared(&hB[0][0]);
    const unsigned hB1 = hB0 + (unsigned)(H_ * sizeof(u64));

    float cA = 0.0f, cB = 0.0f;
    sts64(hA0 + j * 8, z2);
    sts64(hB0 + j * 8, z2);

    const float* xbA = x + (size_t)bA * T_;
    const float* xbB = x + (size_t)bB * T_;
    float* obA = out + (size_t)bA * T_;
    float* obB = out + (size_t)bB * T_;

    // ---- gate phase: R8 fused lookahead engine, 8 chains of depth 4 ----
    auto gates = [&](const float* __restrict__ xb, unsigned rd, int t,
                     u64& aif, u64& ago) {
        const int tc_ = (t < T_) ? t : (T_ - 1);
        const float xv = xb[tc_];
        const u64 xd = pk2(xv, xv);

        u64 a0 = fma2(xd, wih_if, bs_if);
        u64 g0 = fma2(xd, wih_go, bs_go);
        u64 a1 = z2, a2 = z2, a3 = z2;
        u64 g1 = z2, g2 = z2, g3 = z2;

        u64 p0, p1, p2, p3;
        lds2(p0, p1, rd);
        lds2(p2, p3, rd + 16);
#pragma unroll
        for (int k = 0; k < H_ - 4; k += 4) {
            u64 q0, q1, q2, q3;
            lds2(q0, q1, rd + (k + 4) * 8);        // next group, issued early
            lds2(q2, q3, rd + (k + 4) * 8 + 16);
            a0 = fma2(p0, wif[k],     a0);
            g0 = fma2(p0, wgo[k],     g0);
            a1 = fma2(p1, wif[k + 1], a1);
            g1 = fma2(p1, wgo[k + 1], g1);
            a2 = fma2(p2, wif[k + 2], a2);
            g2 = fma2(p2, wgo[k + 2], g2);
            a3 = fma2(p3, wif[k + 3], a3);
            g3 = fma2(p3, wgo[k + 3], g3);
            p0 = q0; p1 = q1; p2 = q2; p3 = q3;
        }
        {
            const int k = H_ - 4;
            a0 = fma2(p0, wif[k],     a0);
            g0 = fma2(p0, wgo[k],     g0);
            a1 = fma2(p1, wif[k + 1], a1);
            g1 = fma2(p1, wgo[k + 1], g1);
            a2 = fma2(p2, wif[k + 2], a2);
            g2 = fma2(p2, wgo[k + 2], g2);
            a3 = fma2(p3, wif[k + 3], a3);
            g3 = fma2(p3, wgo[k + 3], g3);
        }
        aif = add2(add2(a0, a1), add2(a2, a3));
        ago = add2(add2(g0, g1), add2(g2, g3));
    };

    // ---- tail phase: activations, c/h update, h broadcast, pbuf write ----
    auto tail = [&](u64 aif, u64 ago, float& c, unsigned wr,
                    volatile float (*pv)[33], int tt) {
        float ai, af, ag, ao;
        upk2(aif, ai, af);
        upk2(ago, ag, ao);
        const float ti = tanhf_(ai);
        const float tf = tanhf_(af);
        const float g_ = tanhf_(ag);
        const float to = tanhf_(ao);
        const float i_ = fmaf(ti, 0.5f, 0.5f);
        const float f_ = fmaf(tf, 0.5f, 0.5f);
        const float o_ = fmaf(to, 0.5f, 0.5f);
        c = fmaf(f_, c, i_ * g_);
        const float h = o_ * tanhf_(c);
        sts64(wr, pk2(h, h));
        pv[tt][j] = h * wout;
    };

    // Prologue: A's gate phase for t=0 (h(0) seeded at parity 0).
    u64 aifA, agoA, aifB, agoB;
    gates(xbA, hA0, 0, aifA, agoA);

    for (int t0 = 0; t0 < T_; t0 += 32) {
#pragma unroll 2
        for (int tt = 0; tt < 32; ++tt) {
            const int t = t0 + tt;
            // h(t) lives at parity (t&1); tail(t) writes parity (t+1)&1.
            const unsigned rdB = (t & 1) ? hB1 : hB0;
            const unsigned wrA = (((t + 1) & 1) ? hA1 : hA0) + j * 8;
            const unsigned rdA1 = ((t + 1) & 1) ? hA1 : hA0;
            const unsigned wrB = (((t + 1) & 1) ? hB1 : hB0) + j * 8;

            // gatesB(t) || tailA(t): fully independent, ptxas interleaves.
            gates(xbB, rdB, t, aifB, agoB);
            tail(aifA, agoA, cA, wrA, pvA, tt);

            // gatesA(t+1) || tailB(t): gatesA reads hA stored by tailA above
            // (same warp, LSU-ordered).
            gates(xbA, rdA1, t + 1, aifA, agoA);
            tail(aifB, agoB, cB, wrB, pvB, tt);
        }
        // Transposed reductions: lane j sums the 32 partials of timestep t0+j.
        float sA0 = 0.0f, sA1 = 0.0f, sA2 = 0.0f, sA3 = 0.0f;
        float sB0 = 0.0f, sB1 = 0.0f, sB2 = 0.0f, sB3 = 0.0f;
#pragma unroll
        for (int k = 0; k < 32; k += 4) {
            sA0 += pvA[j][k];
            sB0 += pvB[j][k];
            sA1 += pvA[j][k + 1];
            sB1 += pvB[j][k + 1];
            sA2 += pvA[j][k + 2];
            sB2 += pvB[j][k + 2];
            sA3 += pvA[j][k + 3];
            sB3 += pvB[j][k + 3];
        }
        obA[t0 + j] = (sA0 + sA1) + (sA2 + sA3) + bout;
        obB[t0 + j] = (sB0 + sB1) + (sB2 + sB3) + bout;
    }
}

extern "C" void kernel_launch(void* const* d_in, const int* in_sizes, int n_in,
                              void* d_out, int out_size) {
    const float* x     = (const float*)d_in[0];
    const float* W_ih  = (const float*)d_in[1];
    const float* W_hh  = (const float*)d_in[2];
    const float* b_ih  = (const float*)d_in[3];
    const float* b_hh  = (const float*)d_in[4];
    const float* W_out = (const float*)d_in[5];
    const float* b_out = (const float*)d_in[6];
    float* out = (float*)d_out;

    lstm_kernel<<<B_ / 2, 32>>>(x, W_ih, W_hh, b_ih, b_hh, W_out, b_out, out);
}

// round 11
// speedup vs baseline: 1.5150x; 1.1749x over previous
#include <cuda_runtime.h>

// LSTM: B=1024, T=2048, H=32, I=1.
// One warp per batch element; lane j owns hidden unit j.
// GEMV on the fp16 pipe: h broadcast as fp16[32] in smem (4x LDS.128/step),
// k-pair packed fp16x2 weights, 64 HFMA2/step in 8 chains (rt=2 => 2x fp32
// MAC throughput). c, x/bias terms, and activations stay fp32.
// sigmoid(a)=0.5*tanh(a/2)+0.5 with pre-scaled weights; MUFU.TANH.

#define B_ 1024
#define T_ 2048
#define H_ 32

typedef unsigned int u32;

static __device__ __forceinline__ u32 hfma2(u32 a, u32 b, u32 c) {
    u32 d;
    asm("fma.rn.f16x2 %0, %1, %2, %3;" : "=r"(d) : "r"(a), "r"(b), "r"(c));
    return d;
}
static __device__ __forceinline__ u32 hadd2(u32 a, u32 b) {
    u32 d;
    asm("add.rn.f16x2 %0, %1, %2;" : "=r"(d) : "r"(a), "r"(b));
    return d;
}
static __device__ __forceinline__ u32 prmt_swap(u32 a) {
    u32 d;
    asm("prmt.b32 %0, %1, 0, 0x1032;" : "=r"(d) : "r"(a));
    return d;
}
// pack (lo, hi) fp32 -> fp16x2 : d.lo = cvt(lo), d.hi = cvt(hi)
static __device__ __forceinline__ u32 pkh2(float lo, float hi) {
    u32 d;
    asm("cvt.rn.f16x2.f32 %0, %1, %2;" : "=r"(d) : "f"(hi), "f"(lo));
    return d;
}
static __device__ __forceinline__ float f16lo(u32 v) {
    unsigned short lo, hi;
    float f;
    asm("mov.b32 {%0, %1}, %2;" : "=h"(lo), "=h"(hi) : "r"(v));
    asm("cvt.f32.f16 %0, %1;" : "=f"(f) : "h"(lo));
    return f;
}
static __device__ __forceinline__ unsigned short f32_to_h(float f) {
    unsigned short h;
    asm("cvt.rn.f16.f32 %0, %1;" : "=h"(h) : "f"(f));
    return h;
}
static __device__ __forceinline__ float tanhf_(float x) {
    float r; asm("tanh.approx.f32 %0, %1;" : "=f"(r) : "f"(x)); return r;
}
static __device__ __forceinline__ void lds128(u32& r0, u32& r1, u32& r2, u32& r3,
                                              unsigned addr) {
    asm volatile("ld.shared.v4.b32 {%0, %1, %2, %3}, [%4];"
                 : "=r"(r0), "=r"(r1), "=r"(r2), "=r"(r3) : "r"(addr));
}
static __device__ __forceinline__ void sts16(unsigned addr, unsigned short v) {
    asm volatile("st.shared.b16 [%0], %1;" :: "r"(addr), "h"(v));
}

__global__ void __launch_bounds__(32)
lstm_kernel(const float* __restrict__ x,
            const float* __restrict__ W_ih,
            const float* __restrict__ W_hh,
            const float* __restrict__ b_ih,
            const float* __restrict__ b_hh,
            const float* __restrict__ W_out,
            const float* __restrict__ b_out,
            float* __restrict__ out) {
    const int j = threadIdx.x;   // hidden unit
    const int b = blockIdx.x;    // batch element

    __shared__ __align__(16) unsigned short hb16[2][H_];  // fp16 h, double-buffered
    __shared__ float pbuf[32][33];                        // output partials
    volatile float (*pv)[33] = (volatile float (*)[33])pbuf;

    const float sI = 0.5f, sF = 0.5f, sG = 1.0f, sO = 0.5f;

    // fp16x2 k-pair packed recurrent weights, per gate (16 u32 each).
    u32 wi[16], wf[16], wg[16], wo[16];
#pragma unroll
    for (int m = 0; m < 16; m++) {
        const int k = 2 * m;
        wi[m] = pkh2(sI * W_hh[(0 * H_ + j) * H_ + k], sI * W_hh[(0 * H_ + j) * H_ + k + 1]);
        wf[m] = pkh2(sF * W_hh[(1 * H_ + j) * H_ + k], sF * W_hh[(1 * H_ + j) * H_ + k + 1]);
        wg[m] = pkh2(sG * W_hh[(2 * H_ + j) * H_ + k], sG * W_hh[(2 * H_ + j) * H_ + k + 1]);
        wo[m] = pkh2(sO * W_hh[(3 * H_ + j) * H_ + k], sO * W_hh[(3 * H_ + j) * H_ + k + 1]);
    }
    // fp32 input weights and combined biases (pre-scaled).
    const float wihi = sI * W_ih[0 * H_ + j], bsi = sI * (b_ih[0 * H_ + j] + b_hh[0 * H_ + j]);
    const float wihf = sF * W_ih[1 * H_ + j], bsf = sF * (b_ih[1 * H_ + j] + b_hh[1 * H_ + j]);
    const float wihg = sG * W_ih[2 * H_ + j], bsg = sG * (b_ih[2 * H_ + j] + b_hh[2 * H_ + j]);
    const float wiho = sO * W_ih[3 * H_ + j], bso = sO * (b_ih[3 * H_ + j] + b_hh[3 * H_ + j]);
    const float wout = W_out[j];
    const float bout = b_out[0];

    const unsigned hb0 = (unsigned)__cvta_generic_to_shared(&hb16[0][0]);
    const unsigned hb1 = hb0 + (unsigned)(H_ * sizeof(unsigned short));

    float c = 0.0f;
    sts16(hb0 + j * 2, (unsigned short)0);   // h_{-1} = 0 (fp16 zero)

    const float* xb = x + (size_t)b * T_;
    float* ob = out + (size_t)b * T_;
    float xc = xb[0];

    for (int t0 = 0; t0 < T_; t0 += 32) {
#pragma unroll 2
        for (int tt = 0; tt < 32; ++tt) {
            const int t = t0 + tt;
            const int tn = (t + 1 < T_) ? (t + 1) : (T_ - 1);
            const float xn = xb[tn];   // prefetch next x

            const unsigned rd = (t & 1) ? hb1 : hb0;
            const unsigned wr = (((t & 1) ? hb0 : hb1)) + j * 2;

            // Load the full fp16 h vector: 4x LDS.128 (broadcast).
            u32 hp[16];
            lds128(hp[0],  hp[1],  hp[2],  hp[3],  rd);
            lds128(hp[4],  hp[5],  hp[6],  hp[7],  rd + 16);
            lds128(hp[8],  hp[9],  hp[10], hp[11], rd + 32);
            lds128(hp[12], hp[13], hp[14], hp[15], rd + 48);

            // fp32 x+bias part per gate (overlaps LDS latency).
            const float xbi = fmaf(xc, wihi, bsi);
            const float xbf = fmaf(xc, wihf, bsf);
            const float xbg = fmaf(xc, wihg, bsg);
            const float xbo = fmaf(xc, wiho, bso);

            // 8 fp16x2 chains (4 gates x 2), depth 8.
            u32 ai0 = 0u, ai1 = 0u, af0 = 0u, af1 = 0u;
            u32 ag0 = 0u, ag1 = 0u, ao0 = 0u, ao1 = 0u;
#pragma unroll
            for (int m = 0; m < 16; m += 2) {
                ai0 = hfma2(hp[m],     wi[m],     ai0);
                af0 = hfma2(hp[m],     wf[m],     af0);
                ag0 = hfma2(hp[m],     wg[m],     ag0);
                ao0 = hfma2(hp[m],     wo[m],     ao0);
                ai1 = hfma2(hp[m + 1], wi[m + 1], ai1);
                af1 = hfma2(hp[m + 1], wf[m + 1], af1);
                ag1 = hfma2(hp[m + 1], wg[m + 1], ag1);
                ao1 = hfma2(hp[m + 1], wo[m + 1], ao1);
            }
            // Merge: (even,odd) halves -> scalar fp32 preacts.
            u32 si = hadd2(ai0, ai1); si = hadd2(si, prmt_swap(si));
            u32 sf = hadd2(af0, af1); sf = hadd2(sf, prmt_swap(sf));
            u32 sg = hadd2(ag0, ag1); sg = hadd2(sg, prmt_swap(sg));
            u32 so = hadd2(ao0, ao1); so = hadd2(so, prmt_swap(so));

            const float pi = f16lo(si) + xbi;
            const float pf = f16lo(sf) + xbf;
            const float pg = f16lo(sg) + xbg;
            const float po = f16lo(so) + xbo;

            const float ti = tanhf_(pi);
            const float tf = tanhf_(pf);
            const float g_ = tanhf_(pg);
            const float to = tanhf_(po);

            const float i_ = fmaf(ti, 0.5f, 0.5f);
            const float f_ = fmaf(tf, 0.5f, 0.5f);
            const float o_ = fmaf(to, 0.5f, 0.5f);

            c = fmaf(f_, c, i_ * g_);
            const float h = o_ * tanhf_(c);

            sts16(wr, f32_to_h(h));        // fp16 h broadcast (converged warp)
            pv[tt][j] = h * wout;
            xc = xn;
        }
        // Transposed reduction: lane j sums the 32 partials of timestep t0+j.
        float s0 = 0.0f, s1 = 0.0f, s2 = 0.0f, s3 = 0.0f;
#pragma unroll
        for (int k = 0; k < 32; k += 4) {
            s0 += pv[j][k];
            s1 += pv[j][k + 1];
            s2 += pv[j][k + 2];
            s3 += pv[j][k + 3];
        }
        ob[t0 + j] = (s0 + s1) + (s2 + s3) + bout;
    }
}

extern "C" void kernel_launch(void* const* d_in, const int* in_sizes, int n_in,
                              void* d_out, int out_size) {
    const float* x     = (const float*)d_in[0];
    const float* W_ih  = (const float*)d_in[1];
    const float* W_hh  = (const float*)d_in[2];
    const float* b_ih  = (const float*)d_in[3];
    const float* b_hh  = (const float*)d_in[4];
    const float* W_out = (const float*)d_in[5];
    const float* b_out = (const float*)d_in[6];
    float* out = (float*)d_out;

    lstm_kernel<<<B_, 32>>>(x, W_ih, W_hh, b_ih, b_hh, W_out, b_out, out);
}

// round 12
// speedup vs baseline: 1.5850x; 1.0462x over previous
#include <cuda_runtime.h>

// LSTM: B=1024, T=2048, H=32, I=1.
// One warp per batch element; lane j owns hidden unit j.
// fp16-pipe GEMV, GATE-MAJOR schedule: per gate 16 HFMA2 (2 chains x depth 8)
// immediately followed by that gate's merge + MUFU.TANH, so each gate's tail
// hides under the next gate's HFMA2 stream. Order: f, i, g (c-fma early), o.
// h broadcast as fp16[32] in smem (4x LDS.128). c/x/bias/activations fp32.
// sigmoid(a)=0.5*tanh(a/2)+0.5 with pre-scaled weights.

#define B_ 1024
#define T_ 2048
#define H_ 32

typedef unsigned int u32;
typedef unsigned long long u64;

static __device__ __forceinline__ u32 hfma2(u32 a, u32 b, u32 c) {
    u32 d;
    asm("fma.rn.f16x2 %0, %1, %2, %3;" : "=r"(d) : "r"(a), "r"(b), "r"(c));
    return d;
}
static __device__ __forceinline__ u32 hadd2(u32 a, u32 b) {
    u32 d;
    asm("add.rn.f16x2 %0, %1, %2;" : "=r"(d) : "r"(a), "r"(b));
    return d;
}
static __device__ __forceinline__ u32 prmt_swap(u32 a) {
    u32 d;
    asm("prmt.b32 %0, %1, 0, 0x1032;" : "=r"(d) : "r"(a));
    return d;
}
static __device__ __forceinline__ u32 pkh2(float lo, float hi) {
    u32 d;
    asm("cvt.rn.f16x2.f32 %0, %1, %2;" : "=r"(d) : "f"(hi), "f"(lo));
    return d;
}
static __device__ __forceinline__ float f16lo(u32 v) {
    unsigned short lo, hi;
    float f;
    asm("mov.b32 {%0, %1}, %2;" : "=h"(lo), "=h"(hi) : "r"(v));
    asm("cvt.f32.f16 %0, %1;" : "=f"(f) : "h"(lo));
    return f;
}
static __device__ __forceinline__ unsigned short f32_to_h(float f) {
    unsigned short h;
    asm("cvt.rn.f16.f32 %0, %1;" : "=h"(h) : "f"(f));
    return h;
}
static __device__ __forceinline__ float tanhf_(float x) {
    float r; asm("tanh.approx.f32 %0, %1;" : "=f"(r) : "f"(x)); return r;
}
static __device__ __forceinline__ void lds128(u32& r0, u32& r1, u32& r2, u32& r3,
                                              unsigned addr) {
    asm volatile("ld.shared.v4.b32 {%0, %1, %2, %3}, [%4];"
                 : "=r"(r0), "=r"(r1), "=r"(r2), "=r"(r3) : "r"(addr));
}
static __device__ __forceinline__ void sts16(unsigned addr, unsigned short v) {
    asm volatile("st.shared.b16 [%0], %1;" :: "r"(addr), "h"(v));
}
static __device__ __forceinline__ u64 pk2f(float lo, float hi) {
    u64 r;
    asm("mov.b64 %0, {%1, %2};" : "=l"(r) : "f"(lo), "f"(hi));
    return r;
}
static __device__ __forceinline__ void upk2f(u64 v, float& lo, float& hi) {
    asm("mov.b64 {%0, %1}, %2;" : "=f"(lo), "=f"(hi) : "l"(v));
}
static __device__ __forceinline__ u64 fma2f(u64 a, u64 b, u64 c) {
    u64 d;
    asm("fma.rn.f32x2 %0, %1, %2, %3;" : "=l"(d) : "l"(a), "l"(b), "l"(c));
    return d;
}

// One gate: 2 HFMA2 chains (depth 8) over hp[0..15], merge to scalar fp32 + xb.
#define GATE_DOT(W, XB, OUT)                                         \
    do {                                                             \
        u32 c0 = 0u, c1 = 0u;                                        \
        _Pragma("unroll")                                            \
        for (int m = 0; m < 16; m += 2) {                            \
            c0 = hfma2(hp[m],     (W)[m],     c0);                   \
            c1 = hfma2(hp[m + 1], (W)[m + 1], c1);                   \
        }                                                            \
        u32 s = hadd2(c0, c1);                                       \
        s = hadd2(s, prmt_swap(s));                                  \
        (OUT) = f16lo(s) + (XB);                                     \
    } while (0)

__global__ void __launch_bounds__(32)
lstm_kernel(const float* __restrict__ x,
            const float* __restrict__ W_ih,
            const float* __restrict__ W_hh,
            const float* __restrict__ b_ih,
            const float* __restrict__ b_hh,
            const float* __restrict__ W_out,
            const float* __restrict__ b_out,
            float* __restrict__ out) {
    const int j = threadIdx.x;   // hidden unit
    const int b = blockIdx.x;    // batch element

    __shared__ __align__(16) unsigned short hb16[2][H_];  // fp16 h, double-buffered
    __shared__ float pbuf[32][33];                        // output partials
    volatile float (*pv)[33] = (volatile float (*)[33])pbuf;

    const float sI = 0.5f, sF = 0.5f, sG = 1.0f, sO = 0.5f;

    // fp16x2 k-pair packed recurrent weights, per gate.
    u32 wi[16], wf[16], wg[16], wo[16];
#pragma unroll
    for (int m = 0; m < 16; m++) {
        const int k = 2 * m;
        wi[m] = pkh2(sI * W_hh[(0 * H_ + j) * H_ + k], sI * W_hh[(0 * H_ + j) * H_ + k + 1]);
        wf[m] = pkh2(sF * W_hh[(1 * H_ + j) * H_ + k], sF * W_hh[(1 * H_ + j) * H_ + k + 1]);
        wg[m] = pkh2(sG * W_hh[(2 * H_ + j) * H_ + k], sG * W_hh[(2 * H_ + j) * H_ + k + 1]);
        wo[m] = pkh2(sO * W_hh[(3 * H_ + j) * H_ + k], sO * W_hh[(3 * H_ + j) * H_ + k + 1]);
    }
    // fp32 input weights / biases, packed (i,f) and (g,o) for FFMA2.
    const u64 wih_if = pk2f(sI * W_ih[0 * H_ + j], sF * W_ih[1 * H_ + j]);
    const u64 wih_go = pk2f(sG * W_ih[2 * H_ + j], sO * W_ih[3 * H_ + j]);
    const u64 bs_if  = pk2f(sI * (b_ih[0 * H_ + j] + b_hh[0 * H_ + j]),
                            sF * (b_ih[1 * H_ + j] + b_hh[1 * H_ + j]));
    const u64 bs_go  = pk2f(sG * (b_ih[2 * H_ + j] + b_hh[2 * H_ + j]),
                            sO * (b_ih[3 * H_ + j] + b_hh[3 * H_ + j]));
    const float wout = W_out[j];
    const float bout = b_out[0];

    const unsigned hb0 = (unsigned)__cvta_generic_to_shared(&hb16[0][0]);
    const unsigned hb1 = hb0 + (unsigned)(H_ * sizeof(unsigned short));

    float c = 0.0f;
    sts16(hb0 + j * 2, (unsigned short)0);   // h_{-1} = 0

    const float* xb = x + (size_t)b * T_;
    float* ob = out + (size_t)b * T_;
    float xc = xb[0];

    for (int t0 = 0; t0 < T_; t0 += 32) {
#pragma unroll 4
        for (int tt = 0; tt < 32; ++tt) {
            const int t = t0 + tt;
            const int tn = (t + 1 < T_) ? (t + 1) : (T_ - 1);
            const float xn = xb[tn];   // prefetch next x

            const unsigned rd = (t & 1) ? hb1 : hb0;
            const unsigned wr = (((t & 1) ? hb0 : hb1)) + j * 2;

            // Load full fp16 h vector: 4x LDS.128 broadcast.
            u32 hp[16];
            lds128(hp[0],  hp[1],  hp[2],  hp[3],  rd);
            lds128(hp[4],  hp[5],  hp[6],  hp[7],  rd + 16);
            lds128(hp[8],  hp[9],  hp[10], hp[11], rd + 32);
            lds128(hp[12], hp[13], hp[14], hp[15], rd + 48);

            // fp32 x+bias terms via 2x FFMA2 (overlaps LDS latency).
            const u64 xd = pk2f(xc, xc);
            float xbi, xbf, xbg, xbo;
            upk2f(fma2f(xd, wih_if, bs_if), xbi, xbf);
            upk2f(fma2f(xd, wih_go, bs_go), xbg, xbo);

            // Gate-major: each gate's merge+tanh hides under the next gate's
            // HFMA2 stream. Order f, i, g (c-path early), o.
            float pf, pi, pg, po;
            GATE_DOT(wf, xbf, pf);
            const float tf = tanhf_(pf);
            GATE_DOT(wi, xbi, pi);
            const float ti = tanhf_(pi);
            GATE_DOT(wg, xbg, pg);
            const float g_ = tanhf_(pg);
            GATE_DOT(wo, xbo, po);
            const float to = tanhf_(po);

            const float f_ = fmaf(tf, 0.5f, 0.5f);
            const float i_ = fmaf(ti, 0.5f, 0.5f);
            c = fmaf(f_, c, i_ * g_);
            const float tc = tanhf_(c);
            const float o_ = fmaf(to, 0.5f, 0.5f);
            const float h = o_ * tc;

            sts16(wr, f32_to_h(h));        // fp16 h broadcast (converged warp)
            pv[tt][j] = h * wout;
            xc = xn;
        }
        // Transposed reduction: lane j sums the 32 partials of timestep t0+j.
        float s0 = 0.0f, s1 = 0.0f, s2 = 0.0f, s3 = 0.0f;
#pragma unroll
        for (int k = 0; k < 32; k += 4) {
            s0 += pv[j][k];
            s1 += pv[j][k + 1];
            s2 += pv[j][k + 2];
            s3 += pv[j][k + 3];
        }
        ob[t0 + j] = (s0 + s1) + (s2 + s3) + bout;
    }
}

extern "C" void kernel_launch(void* const* d_in, const int* in_sizes, int n_in,
                              void* d_out, int out_size) {
    const float* x     = (const float*)d_in[0];
    const float* W_ih  = (const float*)d_in[1];
    const float* W_hh  = (const float*)d_in[2];
    const float* b_ih  = (const float*)d_in[3];
    const float* b_hh  = (const float*)d_in[4];
    const float* W_out = (const float*)d_in[5];
    const float* b_out = (const float*)d_in[6];
    float* out = (float*)d_out;

    lstm_kernel<<<B_, 32>>>(x, W_ih, W_hh, b_ih, b_hh, W_out, b_out, out);
}